// round 3
// baseline (speedup 1.0000x reference)
#include <cuda_runtime.h>
#include <math.h>
#include <cstdint>
#include <cstddef>

#define Bn 16
#define Tn 1024
#define Dn 128
#define Hn 1024
#define On 64
#define NCTA 128
#define NT   256

typedef unsigned long long ull;

// ---------------- device globals (scratch; no allocs allowed) --------------
__device__ float g_fr0[2][Hn * Bn];     // parity-double-buffered fr of layer0, k-major [h][b]
__device__ float g_fr1[2][Hn * Bn];
__device__ unsigned g_count = 0;
__device__ volatile unsigned g_gen = 0;

// ---------------- packed fp32x2 helpers ------------------------------------
__device__ __forceinline__ void fma2(ull& d, ull a, ull b) {
    asm("fma.rn.f32x2 %0, %1, %2, %0;" : "+l"(d) : "l"(a), "l"(b));
}
__device__ __forceinline__ ull mul2(ull a, ull b) {
    ull r; asm("mul.rn.f32x2 %0, %1, %2;" : "=l"(r) : "l"(a), "l"(b)); return r;
}
__device__ __forceinline__ ull add2(ull a, ull b) {
    ull r; asm("add.rn.f32x2 %0, %1, %2;" : "=l"(r) : "l"(a), "l"(b)); return r;
}
__device__ __forceinline__ ull pack2(float x) {
    ull r; unsigned u = __float_as_uint(x);
    asm("mov.b64 %0, {%1, %1};" : "=l"(r) : "r"(u));
    return r;
}

// ---------------- grid barrier (all 128 CTAs co-resident) ------------------
__device__ __forceinline__ void grid_barrier() {
    __threadfence();
    __syncthreads();
    if (threadIdx.x == 0) {
        unsigned gen = g_gen;
        if (atomicAdd(&g_count, 1u) == NCTA - 1u) {
            g_count = 0u;
            __threadfence();
            g_gen = gen + 1u;
        } else {
            while (g_gen == gen) { }
        }
    }
    __syncthreads();
}

// ---------------- SMEM staging: copy k-major [k][16] rows, swizzled --------
// logical slot c (4 floats) of row k stored at physical slot c ^ ((k>>1)&3)
__device__ __forceinline__ void stage_rows(float* sm, const float* __restrict__ src,
                                           int rbase, int nrows, int tid) {
    const float4* s4 = (const float4*)src;
    for (int idx = tid; idx < nrows * 4; idx += NT) {
        int kl = idx >> 2, c = idx & 3;
        int row = rbase + kl;
        float4 v = __ldcg(s4 + idx);
        *(float4*)(sm + row * 16 + ((c ^ ((row >> 1) & 3)) << 2)) = v;
    }
}

// ---------------- register-weight GEMM inner loop --------------------------
// thread (rg = tid/64, tk = tid%64) holds W[4][NJ] for rows rg*4..rg*4+3,
// k-set = strided {tk + 64*j}. Accumulates acc[4 rows][8 batch-pairs].
template<int NJ, int XJ>
__device__ __forceinline__ void mm_rows(const float* __restrict__ sm,
                                        const float (&W)[4][NJ],
                                        ull (&acc)[4][8], int tk) {
#pragma unroll
    for (int j = 0; j < NJ; ++j) {
        int row;
        if (XJ > 0) row = (j < XJ) ? (tk + 64 * j) : (128 + tk + 64 * (j - XJ));
        else        row = tk + 64 * j;
        const int sw = (row >> 1) & 3;
        ull fr2[8];
#pragma unroll
        for (int c = 0; c < 4; ++c) {
            ulonglong2 v = *(const ulonglong2*)(sm + row * 16 + ((c ^ sw) << 2));
            fr2[2 * c] = v.x; fr2[2 * c + 1] = v.y;
        }
#pragma unroll
        for (int r = 0; r < 4; ++r) {
            ull w2 = pack2(W[r][j]);
#pragma unroll
            for (int bp = 0; bp < 8; ++bp) fma2(acc[r][bp], w2, fr2[bp]);
        }
    }
}

#define REDS 257  // ull stride between reduction rows (2-way-conflict pad)

// k-split reduction + leaky-integration update + tanh + publish
__device__ __forceinline__ void reduce_update(float* sm, ull* vbuf, ull (&acc)[4][8],
                                              const float* __restrict__ bias,
                                              float* __restrict__ frdst,
                                              float* __restrict__ states,
                                              int step, int row0, int tid) {
    ull* red = (ull*)sm;
#pragma unroll
    for (int r = 0; r < 4; ++r)
#pragma unroll
        for (int bp = 0; bp < 8; ++bp)
            red[(r * 8 + bp) * REDS + tid] = acc[r][bp];
    __syncthreads();
    if (tid < 128) {
        const int rg = tid >> 5, rr = (tid >> 3) & 3, bp = tid & 7;
        const ull* p = red + (rr * 8 + bp) * REDS + rg * 64;
        ull s = p[0];
#pragma unroll
        for (int k = 1; k < 64; ++k) s = add2(s, p[k]);
        const int lrow = rg * 4 + rr;
        const int h = row0 + lrow;
        ull b2 = pack2(__ldg(bias + h));
        ull v = vbuf[lrow * 8 + bp];
        v = mul2(v, pack2(0.9f));
        fma2(v, add2(s, b2), pack2(0.1f));
        vbuf[lrow * 8 + bp] = v;
        float lo = __uint_as_float((unsigned)(v & 0xffffffffu));
        float hi = __uint_as_float((unsigned)(v >> 32));
        float t0 = tanhf(lo), t1 = tanhf(hi);
        ull fr = ((ull)__float_as_uint(t1) << 32) | (ull)__float_as_uint(t0);
        ((ull*)frdst)[h * 8 + bp] = fr;
        const int b = 2 * bp;
        states[((size_t)b * Tn + step) * Hn + h]       = t0;
        states[((size_t)(b + 1) * Tn + step) * Hn + h] = t1;
    }
}

// ---------------- persistent RNN kernel ------------------------------------
#define SMEM_FLOATS (2048 * 16 + 256)
#define SMEM_BYTES  (SMEM_FLOATS * 4)

__global__ void __launch_bounds__(NT, 1)
rnn_persistent(const float* __restrict__ x,
               const float* __restrict__ Win0, const float* __restrict__ Wrec0,
               const float* __restrict__ b0,
               const float* __restrict__ Win1, const float* __restrict__ Wrec1,
               const float* __restrict__ b1,
               float* __restrict__ states0, float* __restrict__ states1) {
    extern __shared__ float sm[];
    ull* vbuf = (ull*)(sm + 2048 * 16);           // 128 ull of v state
    const int tid = threadIdx.x;
    const int cta = blockIdx.x;
    const bool grp0 = (cta < 64);
    const int rg = tid >> 6, tk = tid & 63;

    // zero v state and parity-1 fr buffers (re-init on every launch/replay)
    if (tid < 128) vbuf[tid] = 0ull;
    {
        int idx = cta * NT + tid;
        if (idx < Hn * Bn) { g_fr0[1][idx] = 0.0f; g_fr1[1][idx] = 0.0f; }
    }

    // load weight tile into registers (loop-invariant)
    float W0[4][18];
    float W1[4][32];
    int row0;
    if (grp0) {
        row0 = cta * 16;
#pragma unroll
        for (int r = 0; r < 4; ++r) {
            const int h = row0 + rg * 4 + r;
#pragma unroll
            for (int j = 0; j < 18; ++j)
                W0[r][j] = (j < 2) ? __ldg(Win0 + (size_t)h * Dn + tk + 64 * j)
                                   : __ldg(Wrec0 + (size_t)h * Hn + tk + 64 * (j - 2));
        }
    } else {
        row0 = (cta - 64) * 16;
#pragma unroll
        for (int r = 0; r < 4; ++r) {
            const int h = row0 + rg * 4 + r;
#pragma unroll
            for (int j = 0; j < 32; ++j)
                W1[r][j] = (j < 16) ? __ldg(Win1 + (size_t)h * Hn + tk + 64 * j)
                                    : __ldg(Wrec1 + (size_t)h * Hn + tk + 64 * (j - 16));
        }
    }
    grid_barrier();

    // pipelined scan: iteration s -> group A computes fr0[s], group B fr1[s-1]
    for (int s = 0; s <= Tn; ++s) {
        if (grp0) {
            if (s < Tn) {
                // stage x[:, s, :] into rows 0..127 (transposed to [d][b], swizzled)
                {
                    const int b = tid >> 4, q = tid & 15;
                    const float* xp = x + ((size_t)b * Tn + s) * Dn + q * 8;
                    float4 a0 = __ldg((const float4*)xp);
                    float4 a1 = __ldg((const float4*)xp + 1);
                    float vals[8] = {a0.x, a0.y, a0.z, a0.w, a1.x, a1.y, a1.z, a1.w};
#pragma unroll
                    for (int m = 0; m < 8; ++m) {
                        int k = q * 8 + m;
                        sm[k * 16 + (((b >> 2) ^ ((k >> 1) & 3)) << 2) + (b & 3)] = vals[m];
                    }
                }
                // stage fr0[s-1] (parity (s-1)&1 == (s+1)&1) into rows 128..1151
                stage_rows(sm, g_fr0[(s + 1) & 1], 128, 1024, tid);
                __syncthreads();
                ull acc[4][8];
#pragma unroll
                for (int r = 0; r < 4; ++r)
#pragma unroll
                    for (int bp = 0; bp < 8; ++bp) acc[r][bp] = 0ull;
                mm_rows<18, 2>(sm, W0, acc, tk);
                __syncthreads();
                reduce_update(sm, vbuf, acc, b0, g_fr0[s & 1], states0, s, row0, tid);
            }
        } else {
            if (s >= 1) {
                stage_rows(sm, g_fr0[(s + 1) & 1], 0, 1024, tid);    // fr0[s-1]
                stage_rows(sm, g_fr1[s & 1],       1024, 1024, tid); // fr1[s-2]
                __syncthreads();
                ull acc[4][8];
#pragma unroll
                for (int r = 0; r < 4; ++r)
#pragma unroll
                    for (int bp = 0; bp < 8; ++bp) acc[r][bp] = 0ull;
                mm_rows<32, 0>(sm, W1, acc, tk);
                __syncthreads();
                reduce_update(sm, vbuf, acc, b1, g_fr1[(s + 1) & 1], states1, s - 1, row0, tid);
            }
        }
        grid_barrier();
    }
}

// ---------------- readout: out = states1 @ W_out^T + b_out -----------------
__global__ void __launch_bounds__(256)
readout_kernel(const float* __restrict__ s1, const float* __restrict__ Wout,
               const float* __restrict__ bout, float* __restrict__ out) {
    __shared__ float ssm[128][36];   // 128 BT-rows x 32 k (padded)
    __shared__ float wsm[32][66];    // k x o (transposed, padded)
    const int tid = threadIdx.x;
    const int rowg0 = blockIdx.x * 128;
    const int rb = tid >> 3, ob = tid & 7;
    ull acc[4][4];
#pragma unroll
    for (int i = 0; i < 4; ++i)
#pragma unroll
        for (int w = 0; w < 4; ++w) acc[i][w] = 0ull;

    for (int kc = 0; kc < 32; ++kc) {
        // stage states1 tile
        {
            const int row = tid >> 1, half = tid & 1;
            const float4* p = (const float4*)(s1 + (size_t)(rowg0 + row) * Hn + kc * 32 + half * 16);
            float4 v0 = __ldg(p), v1 = __ldg(p + 1), v2 = __ldg(p + 2), v3 = __ldg(p + 3);
            float* d = &ssm[row][half * 16];
            ((float4*)d)[0] = v0; ((float4*)d)[1] = v1;
            ((float4*)d)[2] = v2; ((float4*)d)[3] = v3;
        }
        // stage W_out chunk transposed
        {
            const int o = tid >> 2, kq = tid & 3;
#pragma unroll
            for (int u = 0; u < 2; ++u) {
                float4 w = __ldg((const float4*)(Wout + (size_t)o * Hn + kc * 32 + kq * 8 + u * 4));
                wsm[kq * 8 + u * 4 + 0][o] = w.x;
                wsm[kq * 8 + u * 4 + 1][o] = w.y;
                wsm[kq * 8 + u * 4 + 2][o] = w.z;
                wsm[kq * 8 + u * 4 + 3][o] = w.w;
            }
        }
        __syncthreads();
#pragma unroll 4
        for (int k = 0; k < 32; ++k) {
            float sv[4];
#pragma unroll
            for (int i = 0; i < 4; ++i) sv[i] = ssm[rb * 4 + i][k];
            ull wv[4];
#pragma unroll
            for (int w = 0; w < 4; ++w) wv[w] = *(const ull*)&wsm[k][ob * 8 + 2 * w];
#pragma unroll
            for (int i = 0; i < 4; ++i) {
                ull s2 = pack2(sv[i]);
#pragma unroll
                for (int w = 0; w < 4; ++w) fma2(acc[i][w], s2, wv[w]);
            }
        }
        __syncthreads();
    }
#pragma unroll
    for (int i = 0; i < 4; ++i)
#pragma unroll
        for (int w = 0; w < 4; ++w) {
            ull b2 = *(const ull*)(bout + ob * 8 + 2 * w);
            *(ull*)(out + (size_t)(rowg0 + rb * 4 + i) * On + ob * 8 + 2 * w) =
                add2(acc[i][w], b2);
        }
}

// ---------------- host entry ------------------------------------------------
extern "C" void kernel_launch(void* const* d_in, const int* in_sizes, int n_in,
                              void* d_out, int out_size) {
    const float* x     = (const float*)d_in[0];
    const float* Win0  = (const float*)d_in[1];
    const float* Wrec0 = (const float*)d_in[2];
    const float* b0    = (const float*)d_in[3];
    const float* Win1  = (const float*)d_in[4];
    const float* Wrec1 = (const float*)d_in[5];
    const float* b1    = (const float*)d_in[6];
    const float* Wout  = (const float*)d_in[7];
    const float* bout  = (const float*)d_in[8];

    float* out     = (float*)d_out;                    // [B,T,O]
    float* states0 = out + (size_t)Bn * Tn * On;       // [B,T,H]
    float* states1 = states0 + (size_t)Bn * Tn * Hn;   // [B,T,H]

    cudaFuncSetAttribute(rnn_persistent,
                         cudaFuncAttributeMaxDynamicSharedMemorySize, SMEM_BYTES);

    rnn_persistent<<<NCTA, NT, SMEM_BYTES>>>(x, Win0, Wrec0, b0, Win1, Wrec1, b1,
                                             states0, states1);
    readout_kernel<<<(Bn * Tn) / 128, 256>>>(states1, Wout, bout, out);
}